// round 15
// baseline (speedup 1.0000x reference)
#include <cuda_runtime.h>
#include <cuda_fp16.h>
#include <cstdint>

#define HIDDEN   256
#define NHL      4
#define MTILE    64          // points per CTA
#define THREADS  256
#define NPAIR    32          // 4 layers * 8 pairs (each pair = 2 k-slices of 16)
#define IMG_BYTES 8192       // one [n=256][k=16] fp16 image
#define PAIR_BYTES 16384     // two consecutive images
#define NBUF     2

// single fp16 weight image, transposed [n][k], k-interleaved 32B groups
__device__ __align__(16) __half g_w[NHL * HIDDEN * HIDDEN];

// ---- smem layout (bytes) ---- total ~108.3 KB -> 2 CTAs/SM
#define SM_A    0            // A hi [64][512B] fp16 swizzled rows = 32768
#define SM_ALO  32768        // A lo residual, same layout
#define SM_B    65536        // 2 slots x 16KB = 32768
#define SM_BHS  98304        // bh fp32 [4][256]
#define SM_WFS  102400       // wf fp32 [256]
#define SM_W0S  103424       // w0 fp32 [4][256]
#define SM_B0S  107520       // b0 fp32 [256]
#define SM_CS   108544       // coords [64][4]
#define SM_OMG  109568       // omega [64]
#define SM_PS   109824       // head partials [64][4]
#define SM_MBAR 110848       // full[2] + cons[2]
#define SM_TOTAL 110912

// ---- packed fp32x2 helpers ----
__device__ __forceinline__ uint64_t fma2v(uint64_t a, uint64_t b, uint64_t c) {
    uint64_t d; asm("fma.rn.f32x2 %0, %1, %2, %3;" : "=l"(d) : "l"(a), "l"(b), "l"(c)); return d;
}
__device__ __forceinline__ uint64_t mul2(uint64_t a, uint64_t b) {
    uint64_t d; asm("mul.rn.f32x2 %0, %1, %2;" : "=l"(d) : "l"(a), "l"(b)); return d;
}
__device__ __forceinline__ uint64_t add2(uint64_t a, uint64_t b) {
    uint64_t d; asm("add.rn.f32x2 %0, %1, %2;" : "=l"(d) : "l"(a), "l"(b)); return d;
}
__device__ __forceinline__ uint64_t dup2(float x) {
    uint64_t d; asm("mov.b64 %0, {%1, %1};" : "=l"(d) : "f"(x)); return d;
}
__device__ __forceinline__ uint64_t pack2(float lo, float hi) {
    uint64_t d; asm("mov.b64 %0, {%1, %2};" : "=l"(d) : "f"(lo), "f"(hi)); return d;
}
__device__ __forceinline__ void unpack2(float& lo, float& hi, uint64_t v) {
    asm("mov.b64 {%0, %1}, %2;" : "=f"(lo), "=f"(hi) : "l"(v));
}
__device__ __forceinline__ uint64_t c2(float x) {
    uint64_t d; asm("mov.b64 %0, {%1, %1};" : "=l"(d) : "f"(x)); return d;
}
// packed sine: magic range reduction to [-pi,pi] + degree-15 odd poly
__device__ __forceinline__ uint64_t sin2(uint64_t x) {
    uint64_t n = add2(fma2v(x, c2(0.15915494309189535f), c2(12582912.0f)),
                      c2(-12582912.0f));
    uint64_t r = fma2v(n, c2(-6.2831854820251465f), x);
    r = fma2v(n, c2(1.7484555e-7f), r);
    uint64_t r2 = mul2(r, r);
    uint64_t p = c2(-7.6471637e-13f);
    p = fma2v(p, r2, c2(1.6059044e-10f));
    p = fma2v(p, r2, c2(-2.5052108e-8f));
    p = fma2v(p, r2, c2(2.7557319e-6f));
    p = fma2v(p, r2, c2(-1.9841270e-4f));
    p = fma2v(p, r2, c2(8.3333333e-3f));
    p = fma2v(p, r2, c2(-1.6666667e-1f));
    p = fma2v(p, r2, c2(1.0f));
    return mul2(p, r);
}
// pack two fp32 -> fp16x2 (first arg in lower half)
__device__ __forceinline__ uint32_t cvt_f16x2(float lo, float hi) {
    uint32_t r; asm("cvt.rn.f16x2.f32 %0, %1, %2;" : "=r"(r) : "f"(hi), "f"(lo)); return r;
}

__device__ __forceinline__ uint32_t lds32(uint32_t a) {
    uint32_t v; asm volatile("ld.shared.b32 %0, [%1];" : "=r"(v) : "r"(a)); return v;
}
__device__ __forceinline__ void lds64(uint32_t& x, uint32_t& y, uint32_t a) {
    asm volatile("ld.shared.v2.u32 {%0, %1}, [%2];" : "=r"(x), "=r"(y) : "r"(a));
}
__device__ __forceinline__ void sts32(uint32_t a, uint32_t v) {
    asm volatile("st.shared.b32 [%0], %1;" :: "r"(a), "r"(v) : "memory");
}

// ---- mbarrier / bulk copy ----
__device__ __forceinline__ void mbar_init(uint32_t mb, uint32_t cnt) {
    asm volatile("mbarrier.init.shared.b64 [%0], %1;" :: "r"(mb), "r"(cnt) : "memory");
}
__device__ __forceinline__ void mbar_expect_tx(uint32_t mb, uint32_t bytes) {
    asm volatile("mbarrier.arrive.expect_tx.shared.b64 _, [%0], %1;"
                 :: "r"(mb), "r"(bytes) : "memory");
}
__device__ __forceinline__ void mbar_arrive(uint32_t mb) {
    asm volatile("mbarrier.arrive.shared.b64 _, [%0];" :: "r"(mb) : "memory");
}
__device__ __forceinline__ void mbar_wait(uint32_t mb, uint32_t parity) {
    asm volatile(
        "{\n\t.reg .pred P1;\n\t"
        "WL_%=:\n\t"
        "mbarrier.try_wait.parity.acquire.cta.shared::cta.b64 P1, [%0], %1, 0x989680;\n\t"
        "@P1 bra.uni WD_%=;\n\t"
        "bra.uni WL_%=;\n\t"
        "WD_%=:\n\t}"
        :: "r"(mb), "r"(parity) : "memory");
}
__device__ __forceinline__ void bulk_copy(uint32_t sdst, const void* gsrc,
                                          uint32_t bytes, uint32_t mb) {
    asm volatile(
        "cp.async.bulk.shared::cta.global.mbarrier::complete_tx::bytes [%0], [%1], %2, [%3];"
        :: "r"(sdst), "l"(gsrc), "r"(bytes), "r"(mb) : "memory");
}

// mma.sync m16n8k16 fp16 -> fp32
#define MMA(c, a, b) \
    asm volatile("mma.sync.aligned.m16n8k16.row.col.f32.f16.f16.f32 " \
        "{%0,%1,%2,%3}, {%4,%5,%6,%7}, {%8,%9}, {%0,%1,%2,%3};" \
        : "+f"((c)[0]), "+f"((c)[1]), "+f"((c)[2]), "+f"((c)[3]) \
        : "r"((a)[0]), "r"((a)[1]), "r"((a)[2]), "r"((a)[3]), \
          "r"((b)[0]), "r"((b)[1]))

// byte position of k-index kk (0..15) in a 32B k-interleaved group:
// element order [0,1,8,9, 2,3,10,11, 4,5,12,13, 6,7,14,15]
__device__ __host__ __forceinline__ int kbyte(int kk) {
    return ((kk & 6) >> 1) * 8 + ((kk >> 3) & 1) * 4 + (kk & 1) * 2;
}

// ---- prologue: W -> single fp16, transpose to [n][k], k=16 images, k-interleave ----
__global__ void convert_wh_kernel(const float* __restrict__ wh) {
    int idx = blockIdx.x * blockDim.x + threadIdx.x;
    if (idx >= NHL * HIDDEN * HIDDEN) return;
    int l = idx >> 16, r = idx & 65535, k = r >> 8, n = r & 255;
    int img = l * 16 + (k >> 4);
    int off = img * IMG_BYTES + n * 32 + kbyte(k & 15);
    *(__half*)((char*)g_w + off) = __float2half_rn(wh[idx]);
}

// copy pair p (images 2p, 2p+1) into slot p&1
__device__ __forceinline__ void copy_pair(int p, uint32_t sbase, uint32_t mbb) {
    uint32_t b = (uint32_t)(p & 1);
    uint32_t dst = sbase + SM_B + b * PAIR_BYTES;
    uint32_t mb = mbb + b * 8;
    mbar_expect_tx(mb, PAIR_BYTES);
    bulk_copy(dst, (const char*)g_w + (size_t)p * PAIR_BYTES, PAIR_BYTES, mb);
}

__global__ void __launch_bounds__(THREADS, 2)
siren_mma_kernel(const float* __restrict__ coords,
                 const float* __restrict__ ow1, const float* __restrict__ ob1,
                 const float* __restrict__ ow2, const float* __restrict__ ob2,
                 const float* __restrict__ w0,  const float* __restrict__ b0,
                 const float* __restrict__ bh,  const float* __restrict__ wf,
                 const float* __restrict__ bf,  float* __restrict__ out)
{
    extern __shared__ __align__(16) char smem[];
    float* bhs = (float*)(smem + SM_BHS);
    float* wfs = (float*)(smem + SM_WFS);
    float* w0s = (float*)(smem + SM_W0S);
    float* b0s = (float*)(smem + SM_B0S);
    float* cs  = (float*)(smem + SM_CS);
    float* omg = (float*)(smem + SM_OMG);
    float* ps  = (float*)(smem + SM_PS);

    const int tid  = threadIdx.x;
    const int wid  = tid >> 5;
    const int lane = tid & 31;
    const int gid  = lane >> 2;     // 0..7
    const int qd   = lane & 3;      // 0..3
    const int mw   = wid & 1;       // m strip (32 rows)
    const int nw   = wid >> 1;      // n strip (64 cols)
    const long base = (long)blockIdx.x * MTILE;

    const uint32_t sbase = (uint32_t)__cvta_generic_to_shared(smem);
    const uint32_t mbb   = sbase + SM_MBAR;        // full[0..1]
    const uint32_t mbc   = mbb + NBUF * 8;         // cons[0..1]
    const uint32_t swzA  = (uint32_t)gid << 4;     // A row swizzle

    if (tid == 0) {
        #pragma unroll
        for (int b = 0; b < NBUF; b++) {
            mbar_init(mbb + b * 8, 1);
            mbar_init(mbc + b * 8, 8);   // one arrive per warp
        }
        asm volatile("fence.proxy.async.shared::cta;" ::: "memory");
    }
    __syncthreads();
    if (tid == 0) { copy_pair(0, sbase, mbb); copy_pair(1, sbase, mbb); }

    // stage small tensors
    cs[tid]  = coords[base * 4 + tid];
    wfs[tid] = wf[tid];
    b0s[tid] = b0[tid];
    #pragma unroll
    for (int r = 0; r < 4; r++) {
        w0s[tid + 256 * r] = w0[tid + 256 * r];
        bhs[tid + 256 * r] = bh[tid + 256 * r];
    }
    __syncthreads();

    // ---- omega predictor (threads 0..63) ----
    if (tid < MTILE) {
        float p0 = cs[tid * 4 + 0], p1 = cs[tid * 4 + 1];
        float p2 = cs[tid * 4 + 2], p3 = cs[tid * 4 + 3];
        float s = __ldg(ob2);
        #pragma unroll 4
        for (int j = 0; j < 64; j++) {
            float h = __ldg(&ow1[j]) * p0;
            h = fmaf(__ldg(&ow1[64  + j]), p1, h);
            h = fmaf(__ldg(&ow1[128 + j]), p2, h);
            h = fmaf(__ldg(&ow1[192 + j]), p3, h);
            h += __ldg(&ob1[j]);
            h = fmaxf(h, 0.0f);
            s = fmaf(h, __ldg(&ow2[j]), s);
        }
        float sig = 1.0f / (1.0f + __expf(-s));
        omg[tid] = 10.0f + 90.0f * sig;
    }
    __syncthreads();

    // ---- layer 0: A = sin(omega*(coords@w0+b0)) -> smem fp16 hi/lo ----
    {
        const int m0 = wid * 8;
        const int cA = lane * 4, cB = 128 + lane * 4;
        float accA[8][4], accB[8][4];
        #pragma unroll
        for (int i = 0; i < 8; i++)
            #pragma unroll
            for (int j = 0; j < 4; j++) { accA[i][j] = 0.0f; accB[i][j] = 0.0f; }
        #pragma unroll
        for (int k = 0; k < 4; k++) {
            float4 bA = *(const float4*)(w0s + k * HIDDEN + cA);
            float4 bB = *(const float4*)(w0s + k * HIDDEN + cB);
            #pragma unroll
            for (int i = 0; i < 8; i++) {
                float a = cs[(m0 + i) * 4 + k];
                accA[i][0] = fmaf(a, bA.x, accA[i][0]);
                accA[i][1] = fmaf(a, bA.y, accA[i][1]);
                accA[i][2] = fmaf(a, bA.z, accA[i][2]);
                accA[i][3] = fmaf(a, bA.w, accA[i][3]);
                accB[i][0] = fmaf(a, bB.x, accB[i][0]);
                accB[i][1] = fmaf(a, bB.y, accB[i][1]);
                accB[i][2] = fmaf(a, bB.z, accB[i][2]);
                accB[i][3] = fmaf(a, bB.w, accB[i][3]);
            }
        }
        uint64_t biA0 = *(const uint64_t*)(b0s + cA);
        uint64_t biA1 = *(const uint64_t*)(b0s + cA + 2);
        uint64_t biB0 = *(const uint64_t*)(b0s + cB);
        uint64_t biB1 = *(const uint64_t*)(b0s + cB + 2);
        #pragma unroll
        for (int i = 0; i < 8; i++) {
            int m = m0 + i;
            uint32_t swi = (uint32_t)(m & 7) << 4;
            uint32_t rowA = sbase + SM_A + (uint32_t)m * 512;
            uint64_t om2 = dup2(omg[m]);
            uint64_t sv[4];
            sv[0] = sin2(mul2(om2, add2(pack2(accA[i][0], accA[i][1]), biA0)));
            sv[1] = sin2(mul2(om2, add2(pack2(accA[i][2], accA[i][3]), biA1)));
            sv[2] = sin2(mul2(om2, add2(pack2(accB[i][0], accB[i][1]), biB0)));
            sv[3] = sin2(mul2(om2, add2(pack2(accB[i][2], accB[i][3]), biB1)));
            uint32_t boff[4] = { (uint32_t)(cA*2) ^ swi, (uint32_t)(cA*2+4) ^ swi,
                                 (uint32_t)(cB*2) ^ swi, (uint32_t)(cB*2+4) ^ swi };
            #pragma unroll
            for (int j = 0; j < 4; j++) {
                float s0, s1; unpack2(s0, s1, sv[j]);
                uint32_t h = cvt_f16x2(s0, s1);
                __half2 hh = *reinterpret_cast<__half2*>(&h);
                float2 hf = __half22float2(hh);
                uint32_t lo = cvt_f16x2(s0 - hf.x, s1 - hf.y);
                sts32(rowA + boff[j], h);
                sts32(rowA + 32768 + boff[j], lo);
            }
        }
    }

    // ---- 4 hidden layers: act-split fp16 x2 MMA, single fp16 weights ----
    #pragma unroll 1
    for (int l = 0; l < NHL; l++) {
        __syncthreads();   // new A visible to all warps

        float c[2][8][4];
        #pragma unroll
        for (int mt = 0; mt < 2; mt++)
            #pragma unroll
            for (int nt = 0; nt < 8; nt++)
                #pragma unroll
                for (int j = 0; j < 4; j++) c[mt][nt][j] = 0.0f;

        #pragma unroll 1
        for (int pr = 0; pr < 8; pr++) {
            int p = l * 8 + pr;
            int b = p & 1;
            uint32_t par = (uint32_t)((p >> 1) & 1);

            // slice 0 A fragments (hi+lo) — independent of incoming weights
            uint32_t ah[2][4], al[2][4];
            {
                int kg = (pr * 2) * 16;
                uint32_t kA0 = (uint32_t)((kg + qd * 2) * 2) ^ swzA;
                uint32_t kA1 = (uint32_t)((kg + qd * 2 + 8) * 2) ^ swzA;
                #pragma unroll
                for (int mt = 0; mt < 2; mt++) {
                    uint32_t r0 = sbase + SM_A + (uint32_t)(mw*32 + mt*16 + gid) * 512;
                    ah[mt][0] = lds32(r0 + kA0);
                    ah[mt][1] = lds32(r0 + 4096 + kA0);
                    ah[mt][2] = lds32(r0 + kA1);
                    ah[mt][3] = lds32(r0 + 4096 + kA1);
                    uint32_t r1 = r0 + 32768;
                    al[mt][0] = lds32(r1 + kA0);
                    al[mt][1] = lds32(r1 + 4096 + kA0);
                    al[mt][2] = lds32(r1 + kA1);
                    al[mt][3] = lds32(r1 + 4096 + kA1);
                }
            }

            mbar_wait(mbb + b * 8, par);   // pair p weights ready

            uint32_t slot = sbase + SM_B + (uint32_t)b * PAIR_BYTES;
            uint32_t brow = (uint32_t)((nw*64 + gid) * 32 + qd * 8);

            #pragma unroll
            for (int s = 0; s < 2; s++) {
                if (s == 1) {   // slice 1 A fragments
                    int kg = (pr * 2 + 1) * 16;
                    uint32_t kA0 = (uint32_t)((kg + qd * 2) * 2) ^ swzA;
                    uint32_t kA1 = (uint32_t)((kg + qd * 2 + 8) * 2) ^ swzA;
                    #pragma unroll
                    for (int mt = 0; mt < 2; mt++) {
                        uint32_t r0 = sbase + SM_A + (uint32_t)(mw*32 + mt*16 + gid) * 512;
                        ah[mt][0] = lds32(r0 + kA0);
                        ah[mt][1] = lds32(r0 + 4096 + kA0);
                        ah[mt][2] = lds32(r0 + kA1);
                        ah[mt][3] = lds32(r0 + 4096 + kA1);
                        uint32_t r1 = r0 + 32768;
                        al[mt][0] = lds32(r1 + kA0);
                        al[mt][1] = lds32(r1 + 4096 + kA0);
                        al[mt][2] = lds32(r1 + kA1);
                        al[mt][3] = lds32(r1 + 4096 + kA1);
                    }
                }
                uint32_t bAddr = slot + (uint32_t)s * IMG_BYTES + brow;
                uint32_t bfr[8][2];
                #pragma unroll
                for (int nt = 0; nt < 8; nt++)
                    lds64(bfr[nt][0], bfr[nt][1], bAddr + (uint32_t)(nt * 256));
                #pragma unroll
                for (int mt = 0; mt < 2; mt++)
                    #pragma unroll
                    for (int nt = 0; nt < 8; nt++) MMA(c[mt][nt], ah[mt], bfr[nt]);
                #pragma unroll
                for (int mt = 0; mt < 2; mt++)
                    #pragma unroll
                    for (int nt = 0; nt < 8; nt++) MMA(c[mt][nt], al[mt], bfr[nt]);
            }

            // this warp is done with slot b for pair p
            if (lane == 0) mbar_arrive(mbc + b * 8);
            // single producer: refill slot b with pair p+2 once all 8 warps arrived
            if (tid == 0 && p + 2 < NPAIR) {
                mbar_wait(mbc + b * 8, par);
                copy_pair(p + 2, sbase, mbb);
            }
        }

        __syncthreads();   // all warps' MMAs done before A is overwritten

        // ---- epilogue ----
        const float* bhl = bhs + l * 256;
        if (l < NHL - 1) {
            #pragma unroll
            for (int mt = 0; mt < 2; mt++) {
                int m = mw * 32 + mt * 16 + gid;
                uint64_t om0 = dup2(omg[m]);
                uint64_t om8 = dup2(omg[m + 8]);
                uint32_t row0 = sbase + SM_A + (uint32_t)m * 512;
                uint32_t row8 = row0 + 4096;
                #pragma unroll
                for (int nt = 0; nt < 8; nt++) {
                    int n0 = nw * 64 + nt * 8 + qd * 2;
                    uint64_t bias = *(const uint64_t*)(bhl + n0);
                    uint32_t boff = (uint32_t)(n0 * 2) ^ ((uint32_t)(m & 7) << 4);
                    uint32_t boff8 = (uint32_t)(n0 * 2) ^ ((uint32_t)((m + 8) & 7) << 4);
                    uint64_t s0 = sin2(mul2(om0, add2(pack2(c[mt][nt][0], c[mt][nt][1]), bias)));
                    uint64_t s8 = sin2(mul2(om8, add2(pack2(c[mt][nt][2], c[mt][nt][3]), bias)));
                    float x0, x1; unpack2(x0, x1, s0);
                    uint32_t h0 = cvt_f16x2(x0, x1);
                    __half2 hh0 = *reinterpret_cast<__half2*>(&h0);
                    float2 hf0 = __half22float2(hh0);
                    uint32_t l0 = cvt_f16x2(x0 - hf0.x, x1 - hf0.y);
                    sts32(row0 + boff, h0);
                    sts32(row0 + 32768 + boff, l0);
                    float y0, y1; unpack2(y0, y1, s8);
                    uint32_t h8 = cvt_f16x2(y0, y1);
                    __half2 hh8 = *reinterpret_cast<__half2*>(&h8);
                    float2 hf8 = __half22float2(hh8);
                    uint32_t l8 = cvt_f16x2(y0 - hf8.x, y1 - hf8.y);
                    sts32(row8 + boff8, h8);
                    sts32(row8 + 32768 + boff8, l8);
                }
            }
        } else {
            // fused head: sin + dot with wf, quad-shuffle reduce
            #pragma unroll
            for (int mt = 0; mt < 2; mt++) {
                int m = mw * 32 + mt * 16 + gid;
                uint64_t om0 = dup2(omg[m]);
                uint64_t om8 = dup2(omg[m + 8]);
                uint64_t acc0 = 0ull, acc8 = 0ull;
                #pragma unroll
                for (int nt = 0; nt < 8; nt++) {
                    int n0 = nw * 64 + nt * 8 + qd * 2;
                    uint64_t bias = *(const uint64_t*)(bhl + n0);
                    uint64_t wfp  = *(const uint64_t*)(wfs + n0);
                    uint64_t s0 = sin2(mul2(om0, add2(pack2(c[mt][nt][0], c[mt][nt][1]), bias)));
                    uint64_t s8 = sin2(mul2(om8, add2(pack2(c[mt][nt][2], c[mt][nt][3]), bias)));
                    acc0 = fma2v(s0, wfp, acc0);
                    acc8 = fma2v(s8, wfp, acc8);
                }
                float a0, a1; unpack2(a0, a1, acc0); float p0 = a0 + a1;
                float b0v, b1v; unpack2(b0v, b1v, acc8); float p8 = b0v + b1v;
                p0 += __shfl_xor_sync(0xffffffffu, p0, 1);
                p0 += __shfl_xor_sync(0xffffffffu, p0, 2);
                p8 += __shfl_xor_sync(0xffffffffu, p8, 1);
                p8 += __shfl_xor_sync(0xffffffffu, p8, 2);
                if (qd == 0) {
                    ps[m * 4 + nw] = p0;
                    ps[(m + 8) * 4 + nw] = p8;
                }
            }
        }
    }

    __syncthreads();
    if (tid < MTILE)
        out[base + tid] = ps[tid * 4] + ps[tid * 4 + 1] + ps[tid * 4 + 2]
                        + ps[tid * 4 + 3] + __ldg(bf);
}

extern "C" void kernel_launch(void* const* d_in, const int* in_sizes, int n_in,
                              void* d_out, int out_size)
{
    const float* coords = (const float*)d_in[0];
    const float* ow1    = (const float*)d_in[1];
    const float* ob1    = (const float*)d_in[2];
    const float* ow2    = (const float*)d_in[3];
    const float* ob2    = (const float*)d_in[4];
    const float* w0     = (const float*)d_in[5];
    const float* b0     = (const float*)d_in[6];
    const float* wh     = (const float*)d_in[7];
    const float* bh     = (const float*)d_in[8];
    const float* wf     = (const float*)d_in[9];
    const float* bf     = (const float*)d_in[10];
    float* out = (float*)d_out;

    int n = in_sizes[0] / 4;

    convert_wh_kernel<<<(NHL * HIDDEN * HIDDEN + 255) / 256, 256>>>(wh);

    cudaFuncSetAttribute(siren_mma_kernel,
                         cudaFuncAttributeMaxDynamicSharedMemorySize, SM_TOTAL);
    siren_mma_kernel<<<n / MTILE, THREADS, SM_TOTAL>>>(
        coords, ow1, ob1, ow2, ob2, w0, b0, bh, wf, bf, out);
}

// round 16
// speedup vs baseline: 1.5001x; 1.5001x over previous
#include <cuda_runtime.h>
#include <cuda_fp16.h>
#include <cstdint>

#define HIDDEN   256
#define NHL      4
#define MTILE    64          // points per CTA
#define THREADS  256
#define NPAIR    32          // 4 layers * 8 pairs (each pair = 2 k-slices of 16)
#define IMG_BYTES 8192       // one [n=256][k=16] fp16 image
#define PAIR_BYTES 16384     // two consecutive images
#define NBUF     2

// single fp16 weight image, transposed [n][k], k-interleaved 32B groups
__device__ __align__(16) __half g_w[NHL * HIDDEN * HIDDEN];

// ---- smem layout (bytes) ---- total ~78 KB -> 2 CTAs/SM
#define SM_A    0            // A [64][512B] fp16 swizzled rows = 32768
#define SM_B    32768        // 2 slots x 16KB = 32768
#define SM_BHS  65536        // bh fp32 [4][256]
#define SM_WFS  69632        // wf fp32 [256]
#define SM_W0S  70656        // w0 fp32 [4][256]
#define SM_B0S  74752        // b0 fp32 [256]
#define SM_CS   75776        // coords [64][4]
#define SM_OMG  76800        // omega [64]
#define SM_PS   77056        // head partials [64][4]
#define SM_MBAR 78080        // full[2] + cons[2]
#define SM_TOTAL 78112

// ---- packed fp32x2 helpers ----
__device__ __forceinline__ uint64_t fma2v(uint64_t a, uint64_t b, uint64_t c) {
    uint64_t d; asm("fma.rn.f32x2 %0, %1, %2, %3;" : "=l"(d) : "l"(a), "l"(b), "l"(c)); return d;
}
__device__ __forceinline__ uint64_t mul2(uint64_t a, uint64_t b) {
    uint64_t d; asm("mul.rn.f32x2 %0, %1, %2;" : "=l"(d) : "l"(a), "l"(b)); return d;
}
__device__ __forceinline__ uint64_t add2(uint64_t a, uint64_t b) {
    uint64_t d; asm("add.rn.f32x2 %0, %1, %2;" : "=l"(d) : "l"(a), "l"(b)); return d;
}
__device__ __forceinline__ uint64_t dup2(float x) {
    uint64_t d; asm("mov.b64 %0, {%1, %1};" : "=l"(d) : "f"(x)); return d;
}
__device__ __forceinline__ uint64_t pack2(float lo, float hi) {
    uint64_t d; asm("mov.b64 %0, {%1, %2};" : "=l"(d) : "f"(lo), "f"(hi)); return d;
}
__device__ __forceinline__ void unpack2(float& lo, float& hi, uint64_t v) {
    asm("mov.b64 {%0, %1}, %2;" : "=f"(lo), "=f"(hi) : "l"(v));
}
__device__ __forceinline__ uint64_t c2(float x) {
    uint64_t d; asm("mov.b64 %0, {%1, %1};" : "=l"(d) : "f"(x)); return d;
}
// packed sine: magic range reduction to [-pi,pi] + degree-15 odd poly
__device__ __forceinline__ uint64_t sin2(uint64_t x) {
    uint64_t n = add2(fma2v(x, c2(0.15915494309189535f), c2(12582912.0f)),
                      c2(-12582912.0f));
    uint64_t r = fma2v(n, c2(-6.2831854820251465f), x);
    r = fma2v(n, c2(1.7484555e-7f), r);
    uint64_t r2 = mul2(r, r);
    uint64_t p = c2(-7.6471637e-13f);
    p = fma2v(p, r2, c2(1.6059044e-10f));
    p = fma2v(p, r2, c2(-2.5052108e-8f));
    p = fma2v(p, r2, c2(2.7557319e-6f));
    p = fma2v(p, r2, c2(-1.9841270e-4f));
    p = fma2v(p, r2, c2(8.3333333e-3f));
    p = fma2v(p, r2, c2(-1.6666667e-1f));
    p = fma2v(p, r2, c2(1.0f));
    return mul2(p, r);
}
// pack two fp32 -> fp16x2 (first arg in lower half)
__device__ __forceinline__ uint32_t cvt_f16x2(float lo, float hi) {
    uint32_t r; asm("cvt.rn.f16x2.f32 %0, %1, %2;" : "=r"(r) : "f"(hi), "f"(lo)); return r;
}

__device__ __forceinline__ uint32_t lds32(uint32_t a) {
    uint32_t v; asm volatile("ld.shared.b32 %0, [%1];" : "=r"(v) : "r"(a)); return v;
}
__device__ __forceinline__ void lds64(uint32_t& x, uint32_t& y, uint32_t a) {
    asm volatile("ld.shared.v2.u32 {%0, %1}, [%2];" : "=r"(x), "=r"(y) : "r"(a));
}
__device__ __forceinline__ void sts32(uint32_t a, uint32_t v) {
    asm volatile("st.shared.b32 [%0], %1;" :: "r"(a), "r"(v) : "memory");
}

// ---- mbarrier / bulk copy ----
__device__ __forceinline__ void mbar_init(uint32_t mb, uint32_t cnt) {
    asm volatile("mbarrier.init.shared.b64 [%0], %1;" :: "r"(mb), "r"(cnt) : "memory");
}
__device__ __forceinline__ void mbar_expect_tx(uint32_t mb, uint32_t bytes) {
    asm volatile("mbarrier.arrive.expect_tx.shared.b64 _, [%0], %1;"
                 :: "r"(mb), "r"(bytes) : "memory");
}
__device__ __forceinline__ void mbar_arrive(uint32_t mb) {
    asm volatile("mbarrier.arrive.shared.b64 _, [%0];" :: "r"(mb) : "memory");
}
__device__ __forceinline__ void mbar_wait(uint32_t mb, uint32_t parity) {
    asm volatile(
        "{\n\t.reg .pred P1;\n\t"
        "WL_%=:\n\t"
        "mbarrier.try_wait.parity.acquire.cta.shared::cta.b64 P1, [%0], %1, 0x989680;\n\t"
        "@P1 bra.uni WD_%=;\n\t"
        "bra.uni WL_%=;\n\t"
        "WD_%=:\n\t}"
        :: "r"(mb), "r"(parity) : "memory");
}
__device__ __forceinline__ void bulk_copy(uint32_t sdst, const void* gsrc,
                                          uint32_t bytes, uint32_t mb) {
    asm volatile(
        "cp.async.bulk.shared::cta.global.mbarrier::complete_tx::bytes [%0], [%1], %2, [%3];"
        :: "r"(sdst), "l"(gsrc), "r"(bytes), "r"(mb) : "memory");
}

// mma.sync m16n8k16 fp16 -> fp32
#define MMA(c, a, b) \
    asm volatile("mma.sync.aligned.m16n8k16.row.col.f32.f16.f16.f32 " \
        "{%0,%1,%2,%3}, {%4,%5,%6,%7}, {%8,%9}, {%0,%1,%2,%3};" \
        : "+f"((c)[0]), "+f"((c)[1]), "+f"((c)[2]), "+f"((c)[3]) \
        : "r"((a)[0]), "r"((a)[1]), "r"((a)[2]), "r"((a)[3]), \
          "r"((b)[0]), "r"((b)[1]))

// byte position of k-index kk (0..15) in a 32B k-interleaved group:
// element order [0,1,8,9, 2,3,10,11, 4,5,12,13, 6,7,14,15]
__device__ __host__ __forceinline__ int kbyte(int kk) {
    return ((kk & 6) >> 1) * 8 + ((kk >> 3) & 1) * 4 + (kk & 1) * 2;
}

// ---- prologue: W -> single fp16, transpose to [n][k], k=16 images, k-interleave ----
__global__ void convert_wh_kernel(const float* __restrict__ wh) {
    int idx = blockIdx.x * blockDim.x + threadIdx.x;
    if (idx >= NHL * HIDDEN * HIDDEN) return;
    int l = idx >> 16, r = idx & 65535, k = r >> 8, n = r & 255;
    int img = l * 16 + (k >> 4);
    int off = img * IMG_BYTES + n * 32 + kbyte(k & 15);
    *(__half*)((char*)g_w + off) = __float2half_rn(wh[idx]);
}

// copy pair p (images 2p, 2p+1) into slot p&1
__device__ __forceinline__ void copy_pair(int p, uint32_t sbase, uint32_t mbb) {
    uint32_t b = (uint32_t)(p & 1);
    uint32_t dst = sbase + SM_B + b * PAIR_BYTES;
    uint32_t mb = mbb + b * 8;
    mbar_expect_tx(mb, PAIR_BYTES);
    bulk_copy(dst, (const char*)g_w + (size_t)p * PAIR_BYTES, PAIR_BYTES, mb);
}

__global__ void __launch_bounds__(THREADS, 2)
siren_mma_kernel(const float* __restrict__ coords,
                 const float* __restrict__ ow1, const float* __restrict__ ob1,
                 const float* __restrict__ ow2, const float* __restrict__ ob2,
                 const float* __restrict__ w0,  const float* __restrict__ b0,
                 const float* __restrict__ bh,  const float* __restrict__ wf,
                 const float* __restrict__ bf,  float* __restrict__ out)
{
    extern __shared__ __align__(16) char smem[];
    float* bhs = (float*)(smem + SM_BHS);
    float* wfs = (float*)(smem + SM_WFS);
    float* w0s = (float*)(smem + SM_W0S);
    float* b0s = (float*)(smem + SM_B0S);
    float* cs  = (float*)(smem + SM_CS);
    float* omg = (float*)(smem + SM_OMG);
    float* ps  = (float*)(smem + SM_PS);

    const int tid  = threadIdx.x;
    const int wid  = tid >> 5;
    const int lane = tid & 31;
    const int gid  = lane >> 2;     // 0..7
    const int qd   = lane & 3;      // 0..3
    const int mw   = wid & 1;       // m strip (32 rows)
    const int nw   = wid >> 1;      // n strip (64 cols)
    const long base = (long)blockIdx.x * MTILE;

    const uint32_t sbase = (uint32_t)__cvta_generic_to_shared(smem);
    const uint32_t mbb   = sbase + SM_MBAR;        // full[0..1]
    const uint32_t mbc   = mbb + NBUF * 8;         // cons[0..1]
    const uint32_t swzA  = (uint32_t)gid << 4;     // A row swizzle

    if (tid == 0) {
        #pragma unroll
        for (int b = 0; b < NBUF; b++) {
            mbar_init(mbb + b * 8, 1);
            mbar_init(mbc + b * 8, 8);   // one arrive per warp
        }
        asm volatile("fence.proxy.async.shared::cta;" ::: "memory");
    }
    __syncthreads();
    if (tid == 0) { copy_pair(0, sbase, mbb); copy_pair(1, sbase, mbb); }

    // stage small tensors
    cs[tid]  = coords[base * 4 + tid];
    wfs[tid] = wf[tid];
    b0s[tid] = b0[tid];
    #pragma unroll
    for (int r = 0; r < 4; r++) {
        w0s[tid + 256 * r] = w0[tid + 256 * r];
        bhs[tid + 256 * r] = bh[tid + 256 * r];
    }
    __syncthreads();

    // ---- omega predictor (threads 0..63) ----
    if (tid < MTILE) {
        float p0 = cs[tid * 4 + 0], p1 = cs[tid * 4 + 1];
        float p2 = cs[tid * 4 + 2], p3 = cs[tid * 4 + 3];
        float s = __ldg(ob2);
        #pragma unroll 4
        for (int j = 0; j < 64; j++) {
            float h = __ldg(&ow1[j]) * p0;
            h = fmaf(__ldg(&ow1[64  + j]), p1, h);
            h = fmaf(__ldg(&ow1[128 + j]), p2, h);
            h = fmaf(__ldg(&ow1[192 + j]), p3, h);
            h += __ldg(&ob1[j]);
            h = fmaxf(h, 0.0f);
            s = fmaf(h, __ldg(&ow2[j]), s);
        }
        float sig = 1.0f / (1.0f + __expf(-s));
        omg[tid] = 10.0f + 90.0f * sig;
    }
    __syncthreads();

    // ---- layer 0: A = sin(omega*(coords@w0+b0)) -> smem fp16 (swizzled rows) ----
    {
        const int m0 = wid * 8;
        const int cA = lane * 4, cB = 128 + lane * 4;
        float accA[8][4], accB[8][4];
        #pragma unroll
        for (int i = 0; i < 8; i++)
            #pragma unroll
            for (int j = 0; j < 4; j++) { accA[i][j] = 0.0f; accB[i][j] = 0.0f; }
        #pragma unroll
        for (int k = 0; k < 4; k++) {
            float4 bA = *(const float4*)(w0s + k * HIDDEN + cA);
            float4 bB = *(const float4*)(w0s + k * HIDDEN + cB);
            #pragma unroll
            for (int i = 0; i < 8; i++) {
                float a = cs[(m0 + i) * 4 + k];
                accA[i][0] = fmaf(a, bA.x, accA[i][0]);
                accA[i][1] = fmaf(a, bA.y, accA[i][1]);
                accA[i][2] = fmaf(a, bA.z, accA[i][2]);
                accA[i][3] = fmaf(a, bA.w, accA[i][3]);
                accB[i][0] = fmaf(a, bB.x, accB[i][0]);
                accB[i][1] = fmaf(a, bB.y, accB[i][1]);
                accB[i][2] = fmaf(a, bB.z, accB[i][2]);
                accB[i][3] = fmaf(a, bB.w, accB[i][3]);
            }
        }
        uint64_t biA0 = *(const uint64_t*)(b0s + cA);
        uint64_t biA1 = *(const uint64_t*)(b0s + cA + 2);
        uint64_t biB0 = *(const uint64_t*)(b0s + cB);
        uint64_t biB1 = *(const uint64_t*)(b0s + cB + 2);
        #pragma unroll
        for (int i = 0; i < 8; i++) {
            int m = m0 + i;
            uint32_t swi = (uint32_t)(m & 7) << 4;
            uint32_t rowA = sbase + SM_A + (uint32_t)m * 512;
            uint64_t om2 = dup2(omg[m]);
            uint64_t sv[4];
            sv[0] = sin2(mul2(om2, add2(pack2(accA[i][0], accA[i][1]), biA0)));
            sv[1] = sin2(mul2(om2, add2(pack2(accA[i][2], accA[i][3]), biA1)));
            sv[2] = sin2(mul2(om2, add2(pack2(accB[i][0], accB[i][1]), biB0)));
            sv[3] = sin2(mul2(om2, add2(pack2(accB[i][2], accB[i][3]), biB1)));
            uint32_t boff[4] = { (uint32_t)(cA*2) ^ swi, (uint32_t)(cA*2+4) ^ swi,
                                 (uint32_t)(cB*2) ^ swi, (uint32_t)(cB*2+4) ^ swi };
            #pragma unroll
            for (int j = 0; j < 4; j++) {
                float s0, s1; unpack2(s0, s1, sv[j]);
                sts32(rowA + boff[j], cvt_f16x2(s0, s1));
            }
        }
    }

    // ---- 4 hidden layers: single fp16 x single fp16 MMA, pair pipeline ----
    #pragma unroll 1
    for (int l = 0; l < NHL; l++) {
        __syncthreads();   // new A visible to all warps

        float c[2][8][4];
        #pragma unroll
        for (int mt = 0; mt < 2; mt++)
            #pragma unroll
            for (int nt = 0; nt < 8; nt++)
                #pragma unroll
                for (int j = 0; j < 4; j++) c[mt][nt][j] = 0.0f;

        #pragma unroll 1
        for (int pr = 0; pr < 8; pr++) {
            int p = l * 8 + pr;
            int b = p & 1;
            uint32_t par = (uint32_t)((p >> 1) & 1);

            // slice 0 A fragments — independent of incoming weights
            uint32_t ah[2][4];
            {
                int kg = (pr * 2) * 16;
                uint32_t kA0 = (uint32_t)((kg + qd * 2) * 2) ^ swzA;
                uint32_t kA1 = (uint32_t)((kg + qd * 2 + 8) * 2) ^ swzA;
                #pragma unroll
                for (int mt = 0; mt < 2; mt++) {
                    uint32_t r0 = sbase + SM_A + (uint32_t)(mw*32 + mt*16 + gid) * 512;
                    ah[mt][0] = lds32(r0 + kA0);
                    ah[mt][1] = lds32(r0 + 4096 + kA0);
                    ah[mt][2] = lds32(r0 + kA1);
                    ah[mt][3] = lds32(r0 + 4096 + kA1);
                }
            }

            mbar_wait(mbb + b * 8, par);   // pair p weights ready

            uint32_t slot = sbase + SM_B + (uint32_t)b * PAIR_BYTES;
            uint32_t brow = (uint32_t)((nw*64 + gid) * 32 + qd * 8);

            #pragma unroll
            for (int s = 0; s < 2; s++) {
                if (s == 1) {   // slice 1 A fragments
                    int kg = (pr * 2 + 1) * 16;
                    uint32_t kA0 = (uint32_t)((kg + qd * 2) * 2) ^ swzA;
                    uint32_t kA1 = (uint32_t)((kg + qd * 2 + 8) * 2) ^ swzA;
                    #pragma unroll
                    for (int mt = 0; mt < 2; mt++) {
                        uint32_t r0 = sbase + SM_A + (uint32_t)(mw*32 + mt*16 + gid) * 512;
                        ah[mt][0] = lds32(r0 + kA0);
                        ah[mt][1] = lds32(r0 + 4096 + kA0);
                        ah[mt][2] = lds32(r0 + kA1);
                        ah[mt][3] = lds32(r0 + 4096 + kA1);
                    }
                }
                uint32_t bAddr = slot + (uint32_t)s * IMG_BYTES + brow;
                uint32_t bfr[8][2];
                #pragma unroll
                for (int nt = 0; nt < 8; nt++)
                    lds64(bfr[nt][0], bfr[nt][1], bAddr + (uint32_t)(nt * 256));
                #pragma unroll
                for (int mt = 0; mt < 2; mt++)
                    #pragma unroll
                    for (int nt = 0; nt < 8; nt++) MMA(c[mt][nt], ah[mt], bfr[nt]);
            }

            // this warp is done with slot b for pair p
            if (lane == 0) mbar_arrive(mbc + b * 8);
            // single producer: refill slot b with pair p+2 once all 8 warps arrived
            if (tid == 0 && p + 2 < NPAIR) {
                mbar_wait(mbc + b * 8, par);
                copy_pair(p + 2, sbase, mbb);
            }
        }

        __syncthreads();   // all warps' MMAs done before A is overwritten

        // ---- epilogue ----
        const float* bhl = bhs + l * 256;
        if (l < NHL - 1) {
            #pragma unroll
            for (int mt = 0; mt < 2; mt++) {
                int m = mw * 32 + mt * 16 + gid;
                uint64_t om0 = dup2(omg[m]);
                uint64_t om8 = dup2(omg[m + 8]);
                uint32_t row0 = sbase + SM_A + (uint32_t)m * 512;
                uint32_t row8 = row0 + 4096;
                #pragma unroll
                for (int nt = 0; nt < 8; nt++) {
                    int n0 = nw * 64 + nt * 8 + qd * 2;
                    uint64_t bias = *(const uint64_t*)(bhl + n0);
                    uint32_t boff = (uint32_t)(n0 * 2) ^ ((uint32_t)(m & 7) << 4);
                    uint32_t boff8 = (uint32_t)(n0 * 2) ^ ((uint32_t)((m + 8) & 7) << 4);
                    uint64_t s0 = sin2(mul2(om0, add2(pack2(c[mt][nt][0], c[mt][nt][1]), bias)));
                    uint64_t s8 = sin2(mul2(om8, add2(pack2(c[mt][nt][2], c[mt][nt][3]), bias)));
                    float x0, x1; unpack2(x0, x1, s0);
                    sts32(row0 + boff, cvt_f16x2(x0, x1));
                    float y0, y1; unpack2(y0, y1, s8);
                    sts32(row8 + boff8, cvt_f16x2(y0, y1));
                }
            }
        } else {
            // fused head: sin + dot with wf, quad-shuffle reduce
            #pragma unroll
            for (int mt = 0; mt < 2; mt++) {
                int m = mw * 32 + mt * 16 + gid;
                uint64_t om0 = dup2(omg[m]);
                uint64_t om8 = dup2(omg[m + 8]);
                uint64_t acc0 = 0ull, acc8 = 0ull;
                #pragma unroll
                for (int nt = 0; nt < 8; nt++) {
                    int n0 = nw * 64 + nt * 8 + qd * 2;
                    uint64_t bias = *(const uint64_t*)(bhl + n0);
                    uint64_t wfp  = *(const uint64_t*)(wfs + n0);
                    uint64_t s0 = sin2(mul2(om0, add2(pack2(c[mt][nt][0], c[mt][nt][1]), bias)));
                    uint64_t s8 = sin2(mul2(om8, add2(pack2(c[mt][nt][2], c[mt][nt][3]), bias)));
                    acc0 = fma2v(s0, wfp, acc0);
                    acc8 = fma2v(s8, wfp, acc8);
                }
                float a0, a1; unpack2(a0, a1, acc0); float p0 = a0 + a1;
                float b0v, b1v; unpack2(b0v, b1v, acc8); float p8 = b0v + b1v;
                p0 += __shfl_xor_sync(0xffffffffu, p0, 1);
                p0 += __shfl_xor_sync(0xffffffffu, p0, 2);
                p8 += __shfl_xor_sync(0xffffffffu, p8, 1);
                p8 += __shfl_xor_sync(0xffffffffu, p8, 2);
                if (qd == 0) {
                    ps[m * 4 + nw] = p0;
                    ps[(m + 8) * 4 + nw] = p8;
                }
            }
        }
    }

    __syncthreads();
    if (tid < MTILE)
        out[base + tid] = ps[tid * 4] + ps[tid * 4 + 1] + ps[tid * 4 + 2]
                        + ps[tid * 4 + 3] + __ldg(bf);
}

extern "C" void kernel_launch(void* const* d_in, const int* in_sizes, int n_in,
                              void* d_out, int out_size)
{
    const float* coords = (const float*)d_in[0];
    const float* ow1    = (const float*)d_in[1];
    const float* ob1    = (const float*)d_in[2];
    const float* ow2    = (const float*)d_in[3];
    const float* ob2    = (const float*)d_in[4];
    const float* w0     = (const float*)d_in[5];
    const float* b0     = (const float*)d_in[6];
    const float* wh     = (const float*)d_in[7];
    const float* bh     = (const float*)d_in[8];
    const float* wf     = (const float*)d_in[9];
    const float* bf     = (const float*)d_in[10];
    float* out = (float*)d_out;

    int n = in_sizes[0] / 4;

    convert_wh_kernel<<<(NHL * HIDDEN * HIDDEN + 255) / 256, 256>>>(wh);

    cudaFuncSetAttribute(siren_mma_kernel,
                         cudaFuncAttributeMaxDynamicSharedMemorySize, SM_TOTAL);
    siren_mma_kernel<<<n / MTILE, THREADS, SM_TOTAL>>>(
        coords, ow1, ob1, ow2, ob2, w0, b0, bh, wf, bf, out);
}